// round 4
// baseline (speedup 1.0000x reference)
#include <cuda_runtime.h>
#include <math.h>
#include <stdint.h>

// Shapes (fixed by the problem)
//   B=4, T=8, RES=32, C=128 -> L=8192, M=32768 token rows
//   TSP=4, SPLIT=4, per-branch: h=64 channels, nh=4 heads, hd=16, win=512
//   branch0: Hsp=32, Wsp=4 ; branch1: Hsp=4, Wsp=32
//   windows per branch = 64, CTAs = 2*64*4 = 512

#define M_TOK 32768

// Scratch (static device arrays; no runtime allocation)
__device__ float g_norm[M_TOK * 128];   // LN output (reused for LN1 and LN2)
__device__ float g_qkv [M_TOK * 384];   // qkv projection
__device__ float g_att [M_TOK * 128];   // concat attention output (token order)
__device__ float g_hid [M_TOK * 512];   // MLP hidden

// ---------------------------------------------------------------------------
// LayerNorm: one warp per 128-channel row, 4 elems per lane
// ---------------------------------------------------------------------------
__global__ void __launch_bounds__(256) ln_kernel(
    const float* __restrict__ x, const float* __restrict__ w,
    const float* __restrict__ b, float* __restrict__ out)
{
    int lane = threadIdx.x & 31;
    int row  = blockIdx.x * 8 + (threadIdx.x >> 5);
    const float4 v = *(const float4*)(x + (size_t)row * 128 + lane * 4);
    float s = v.x + v.y + v.z + v.w;
    #pragma unroll
    for (int o = 16; o; o >>= 1) s += __shfl_xor_sync(0xffffffffu, s, o);
    float mu = s * (1.0f / 128.0f);
    float dx = v.x - mu, dy = v.y - mu, dz = v.z - mu, dw = v.w - mu;
    float sq = dx * dx + dy * dy + dz * dz + dw * dw;
    #pragma unroll
    for (int o = 16; o; o >>= 1) sq += __shfl_xor_sync(0xffffffffu, sq, o);
    float r = rsqrtf(sq * (1.0f / 128.0f) + 1e-5f);
    float4 wv = *(const float4*)(w + lane * 4);
    float4 bv = *(const float4*)(b + lane * 4);
    float4 o4;
    o4.x = dx * r * wv.x + bv.x;
    o4.y = dy * r * wv.y + bv.y;
    o4.z = dz * r * wv.z + bv.z;
    o4.w = dw * r * wv.w + bv.w;
    *(float4*)(out + (size_t)row * 128 + lane * 4) = o4;
}

// ---------------------------------------------------------------------------
// GEMM: out[M,N] = A[M,K] @ W[N,K]^T (+bias) (+gelu) (+res)
// 64x64 tile, 256 threads, 4x4 per thread, BK=16. M,N multiples of 64; K of 16.
// ---------------------------------------------------------------------------
template <bool GELU>
__global__ void __launch_bounds__(256) gemm_kernel(
    const float* __restrict__ A, const float* __restrict__ W,
    const float* __restrict__ bias, const float* __restrict__ res,
    float* __restrict__ out, int N, int K)
{
    __shared__ float sA[16][68];
    __shared__ float sB[16][68];
    int tx = threadIdx.x & 15, ty = threadIdx.x >> 4;
    int m0 = blockIdx.y << 6, n0 = blockIdx.x << 6;
    int lr = threadIdx.x >> 2;             // 0..63 tile row
    int lc = (threadIdx.x & 3) << 2;       // 0,4,8,12 k-offset

    const float* Ap = A + (size_t)(m0 + lr) * K + lc;
    const float* Wp = W + (size_t)(n0 + lr) * K + lc;

    float acc[4][4] = {};
    for (int k0 = 0; k0 < K; k0 += 16) {
        float4 av = *(const float4*)(Ap + k0);
        float4 wv = *(const float4*)(Wp + k0);
        __syncthreads();
        sA[lc + 0][lr] = av.x; sA[lc + 1][lr] = av.y;
        sA[lc + 2][lr] = av.z; sA[lc + 3][lr] = av.w;
        sB[lc + 0][lr] = wv.x; sB[lc + 1][lr] = wv.y;
        sB[lc + 2][lr] = wv.z; sB[lc + 3][lr] = wv.w;
        __syncthreads();
        #pragma unroll
        for (int kk = 0; kk < 16; kk++) {
            float4 a  = *(const float4*)&sA[kk][ty << 2];
            float4 bb = *(const float4*)&sB[kk][tx << 2];
            float ar[4] = {a.x, a.y, a.z, a.w};
            float br[4] = {bb.x, bb.y, bb.z, bb.w};
            #pragma unroll
            for (int i = 0; i < 4; i++)
                #pragma unroll
                for (int j = 0; j < 4; j++)
                    acc[i][j] = fmaf(ar[i], br[j], acc[i][j]);
        }
    }

    float bz[4] = {0.f, 0.f, 0.f, 0.f};
    if (bias) {
        float4 b4 = *(const float4*)(bias + n0 + (tx << 2));
        bz[0] = b4.x; bz[1] = b4.y; bz[2] = b4.z; bz[3] = b4.w;
    }
    #pragma unroll
    for (int i = 0; i < 4; i++) {
        int row = m0 + (ty << 2) + i;
        float v[4];
        #pragma unroll
        for (int j = 0; j < 4; j++) {
            float t = acc[i][j] + bz[j];
            if (GELU) t = 0.5f * t * (1.0f + erff(t * 0.70710678118654752f));
            v[j] = t;
        }
        size_t off = (size_t)row * N + n0 + (tx << 2);
        if (res) {
            float4 r4 = *(const float4*)(res + off);
            v[0] += r4.x; v[1] += r4.y; v[2] += r4.z; v[3] += r4.w;
        }
        float4 o4 = {v[0], v[1], v[2], v[3]};
        *(float4*)(out + off) = o4;
    }
}

// ---------------------------------------------------------------------------
// Attention + fused LePE (depthwise 3x3x3 conv on V) per (branch, window, head)
// One CTA = one (window, head): q,k,v are (512, 16).
// K,V live in 64KB dynamic SMEM; Q rows in registers; 2-pass streaming softmax.
// ---------------------------------------------------------------------------
__global__ void __launch_bounds__(256) attn_kernel(
    const float* __restrict__ qkv,
    const float* __restrict__ cw0, const float* __restrict__ cb0,
    const float* __restrict__ cw1, const float* __restrict__ cb1,
    float* __restrict__ att)
{
    extern __shared__ float dsm[];
    float* sK = dsm;            // 512*16
    float* sV = dsm + 8192;     // 512*16
    __shared__ float sCW[27 * 16];  // conv weights for this head, [k][d]
    __shared__ float sCB[16];

    int bid = blockIdx.x;
    int br  = bid >> 8;
    int rem = bid & 255;
    int w   = rem >> 2;
    int n   = rem & 3;
    int b   = w >> 4;
    int tb  = (w >> 3) & 1;
    int hw  = w & 7;            // wb for branch0, hb for branch1
    int tid = threadIdx.x;

    // window position p -> within-batch token index l
    auto tok = [&](int p) -> int {
        int ts = p >> 7, r2 = p & 127;
        if (br == 0) {
            int hs = r2 >> 2, ws = r2 & 3;
            return ((tb * 4 + ts) << 10) + (hs << 5) + (hw << 2) + ws;
        } else {
            int hs = r2 >> 5, ws = r2 & 31;
            return ((tb * 4 + ts) << 10) + (((hw << 2) + hs) << 5) + ws;
        }
    };

    int cq = br * 64 + n * 16;     // channel offset inside a 128-wide section
    int rowbase = b * 8192;

    // load K and V tiles into SMEM
    for (int idx = tid; idx < 2048; idx += 256) {
        int p = idx >> 2, c4 = (idx & 3) << 2;
        const float* base = qkv + (size_t)(rowbase + tok(p)) * 384;
        *(float4*)&sK[p * 16 + c4] = *(const float4*)(base + 128 + cq + c4);
        *(float4*)&sV[p * 16 + c4] = *(const float4*)(base + 256 + cq + c4);
    }
    // conv weights for this head's 16 channels, transposed to [k][d]
    {
        const float* cw = br ? cw1 : cw0;
        for (int idx = tid; idx < 432; idx += 256) {
            int d = idx / 27, k = idx - d * 27;
            sCW[k * 16 + d] = cw[(n * 16 + d) * 27 + k];
        }
        if (tid < 16) sCB[tid] = (br ? cb1 : cb0)[n * 16 + tid];
    }
    __syncthreads();

    // each thread owns 2 query rows
    int p0 = tid, p1 = tid + 256;
    int l0t = tok(p0), l1t = tok(p1);
    float q0[16], q1[16];
    {
        const float* qp0 = qkv + (size_t)(rowbase + l0t) * 384 + cq;
        const float* qp1 = qkv + (size_t)(rowbase + l1t) * 384 + cq;
        #pragma unroll
        for (int d4 = 0; d4 < 16; d4 += 4) {
            float4 a = *(const float4*)(qp0 + d4);
            q0[d4] = a.x * 0.25f; q0[d4+1] = a.y * 0.25f;
            q0[d4+2] = a.z * 0.25f; q0[d4+3] = a.w * 0.25f;
            float4 c = *(const float4*)(qp1 + d4);
            q1[d4] = c.x * 0.25f; q1[d4+1] = c.y * 0.25f;
            q1[d4+2] = c.z * 0.25f; q1[d4+3] = c.w * 0.25f;
        }
    }

    // pass 1: row maxima
    float m0 = -1e30f, m1 = -1e30f;
    for (int j = 0; j < 512; j++) {
        const float4* kr = (const float4*)&sK[j * 16];
        float kv[16];
        #pragma unroll
        for (int d4 = 0; d4 < 4; d4++) {
            float4 t = kr[d4];
            kv[d4*4] = t.x; kv[d4*4+1] = t.y; kv[d4*4+2] = t.z; kv[d4*4+3] = t.w;
        }
        float s0 = 0.f, s1 = 0.f;
        #pragma unroll
        for (int d = 0; d < 16; d++) {
            s0 = fmaf(q0[d], kv[d], s0);
            s1 = fmaf(q1[d], kv[d], s1);
        }
        m0 = fmaxf(m0, s0);
        m1 = fmaxf(m1, s1);
    }

    // pass 2: exp-sum + AV accumulation
    float acc0[16] = {}, acc1[16] = {};
    float sum0 = 0.f, sum1 = 0.f;
    for (int j = 0; j < 512; j++) {
        const float4* kr = (const float4*)&sK[j * 16];
        const float4* vr = (const float4*)&sV[j * 16];
        float kv[16], vv[16];
        #pragma unroll
        for (int d4 = 0; d4 < 4; d4++) {
            float4 t = kr[d4];
            kv[d4*4] = t.x; kv[d4*4+1] = t.y; kv[d4*4+2] = t.z; kv[d4*4+3] = t.w;
            float4 u = vr[d4];
            vv[d4*4] = u.x; vv[d4*4+1] = u.y; vv[d4*4+2] = u.z; vv[d4*4+3] = u.w;
        }
        float s0 = 0.f, s1 = 0.f;
        #pragma unroll
        for (int d = 0; d < 16; d++) {
            s0 = fmaf(q0[d], kv[d], s0);
            s1 = fmaf(q1[d], kv[d], s1);
        }
        float e0 = __expf(s0 - m0);
        float e1 = __expf(s1 - m1);
        sum0 += e0; sum1 += e1;
        #pragma unroll
        for (int d = 0; d < 16; d++) {
            acc0[d] = fmaf(e0, vv[d], acc0[d]);
            acc1[d] = fmaf(e1, vv[d], acc1[d]);
        }
    }
    float inv0 = 1.0f / sum0, inv1 = 1.0f / sum1;

    int Hsp = br ? 4 : 32;
    int Wsp = br ? 32 : 4;

    // epilogue: LePE (depthwise 3x3x3 with zero pad inside the window) + write
    auto write_row = [&](int p, int ltok, const float* acc, float inv) {
        int ts = p >> 7, r2 = p & 127;
        int hs = br ? (r2 >> 5) : (r2 >> 2);
        int ws = r2 & (Wsp - 1);
        float lep[16];
        #pragma unroll
        for (int d = 0; d < 16; d++) lep[d] = sCB[d];
        #pragma unroll
        for (int kt = 0; kt < 3; kt++) {
            int t2 = ts + kt - 1;
            if ((unsigned)t2 >= 4u) continue;
            #pragma unroll
            for (int kh = 0; kh < 3; kh++) {
                int h2 = hs + kh - 1;
                if ((unsigned)h2 >= (unsigned)Hsp) continue;
                #pragma unroll
                for (int kw = 0; kw < 3; kw++) {
                    int w2 = ws + kw - 1;
                    if ((unsigned)w2 >= (unsigned)Wsp) continue;
                    int pp = (t2 * Hsp + h2) * Wsp + w2;
                    int kidx = kt * 9 + kh * 3 + kw;
                    const float4* wr4 = (const float4*)&sCW[kidx * 16];
                    const float4* vr4 = (const float4*)&sV[pp * 16];
                    #pragma unroll
                    for (int d4 = 0; d4 < 4; d4++) {
                        float4 wv = wr4[d4];
                        float4 vv = vr4[d4];
                        lep[d4*4+0] = fmaf(wv.x, vv.x, lep[d4*4+0]);
                        lep[d4*4+1] = fmaf(wv.y, vv.y, lep[d4*4+1]);
                        lep[d4*4+2] = fmaf(wv.z, vv.z, lep[d4*4+2]);
                        lep[d4*4+3] = fmaf(wv.w, vv.w, lep[d4*4+3]);
                    }
                }
            }
        }
        float* op = att + (size_t)(rowbase + ltok) * 128 + cq;
        #pragma unroll
        for (int d4 = 0; d4 < 4; d4++) {
            float4 o;
            o.x = acc[d4*4+0] * inv + lep[d4*4+0];
            o.y = acc[d4*4+1] * inv + lep[d4*4+1];
            o.z = acc[d4*4+2] * inv + lep[d4*4+2];
            o.w = acc[d4*4+3] * inv + lep[d4*4+3];
            *(float4*)(op + d4 * 4) = o;
        }
    };
    write_row(p0, l0t, acc0, inv0);
    write_row(p1, l1t, acc1, inv1);
}

// ---------------------------------------------------------------------------
// Launch sequence
// ---------------------------------------------------------------------------
extern "C" void kernel_launch(void* const* d_in, const int* in_sizes, int n_in,
                              void* d_out, int out_size)
{
    const float* x    = (const float*)d_in[0];
    const float* n1w  = (const float*)d_in[1];
    const float* n1b  = (const float*)d_in[2];
    const float* qkvw = (const float*)d_in[3];
    const float* cw0  = (const float*)d_in[4];
    const float* cb0  = (const float*)d_in[5];
    const float* cw1  = (const float*)d_in[6];
    const float* cb1  = (const float*)d_in[7];
    const float* pw   = (const float*)d_in[8];
    const float* pb   = (const float*)d_in[9];
    const float* n2w  = (const float*)d_in[10];
    const float* n2b  = (const float*)d_in[11];
    const float* f1w  = (const float*)d_in[12];
    const float* f1b  = (const float*)d_in[13];
    const float* f2w  = (const float*)d_in[14];
    const float* f2b  = (const float*)d_in[15];
    float* out = (float*)d_out;

    float *pnorm, *pqkv, *patt, *phid;
    cudaGetSymbolAddress((void**)&pnorm, g_norm);
    cudaGetSymbolAddress((void**)&pqkv,  g_qkv);
    cudaGetSymbolAddress((void**)&patt,  g_att);
    cudaGetSymbolAddress((void**)&phid,  g_hid);

    cudaFuncSetAttribute(attn_kernel,
                         cudaFuncAttributeMaxDynamicSharedMemorySize, 65536);

    // 1) LN1
    ln_kernel<<<4096, 256>>>(x, n1w, n1b, pnorm);
    // 2) qkv = LN1(x) @ qkv_w^T   (M x 384)
    gemm_kernel<false><<<dim3(6, 512), 256>>>(pnorm, qkvw, nullptr, nullptr,
                                              pqkv, 384, 128);
    // 3) windowed attention + LePE, both branches
    attn_kernel<<<512, 256, 65536>>>(pqkv, cw0, cb0, cw1, cb1, patt);
    // 4) x2 = x + att @ proj_w^T + proj_b  -> d_out
    gemm_kernel<false><<<dim3(2, 512), 256>>>(patt, pw, pb, x, out, 128, 128);
    // 5) LN2
    ln_kernel<<<4096, 256>>>(out, n2w, n2b, pnorm);
    // 6) hid = gelu(LN2 @ fc1_w^T + fc1_b)  (M x 512)
    gemm_kernel<true><<<dim3(8, 512), 256>>>(pnorm, f1w, f1b, nullptr,
                                             phid, 512, 128);
    // 7) out = x2 + hid @ fc2_w^T + fc2_b
    gemm_kernel<false><<<dim3(2, 512), 256>>>(phid, f2w, f2b, out, out, 128, 512);
}